// round 17
// baseline (speedup 1.0000x reference)
#include <cuda_runtime.h>
#include <math.h>

#define BB 2
#define SS 1024
#define TT 1024
#define DS 128
#define DT 64
#define H 64
#define LN_EPS 1e-5f

#define TILE_T 8
#define CH 32
#define USTRIDE 68   // floats; 272B row stride, 16B-aligned, conflict-free 16B reads
#define TTG 8        // t-rows per transfer block

typedef unsigned long long ull;

__device__ __forceinline__ ull fma2(ull a, ull b, ull c) {
    ull d; asm("fma.rn.f32x2 %0,%1,%2,%3;" : "=l"(d) : "l"(a), "l"(b), "l"(c)); return d;
}
__device__ __forceinline__ ull add2(ull a, ull b) {
    ull d; asm("add.rn.f32x2 %0,%1,%2;" : "=l"(d) : "l"(a), "l"(b)); return d;
}
__device__ __forceinline__ ull pack2(float lo, float hi) {
    ull d; asm("mov.b64 %0,{%1,%2};" : "=l"(d) : "f"(lo), "f"(hi)); return d;
}
__device__ __forceinline__ float2 unpack2(ull v) {
    float2 r; asm("mov.b64 {%0,%1},%2;" : "=f"(r.x), "=f"(r.y) : "l"(v)); return r;
}
__device__ __forceinline__ void cp16(void* smem_dst, const void* gsrc) {
    unsigned sa = (unsigned)__cvta_generic_to_shared(smem_dst);
    asm volatile("cp.async.cg.shared.global [%0], [%1], 16;" :: "r"(sa), "l"(gsrc));
}

// ---------------- scratch ----------------
__device__ float g_s_ad[BB * SS * H];
__device__ float g_u[BB * SS * H];
__device__ float g_t_ad[BB * TT * H];
__device__ float g_a[BB * TT * H];
__device__ float g_sum_u[BB * SS];
__device__ float g_su2[BB * SS];
__device__ float g_sum_a[BB * TT];
__device__ float g_sa2[BB * TT];
__device__ float g_gate[BB * TT];

// constants for score kernel (LDC.128 path)
__constant__ __align__(16) float c_cg[H];
__constant__ __align__(16) float c_cb[H];
__constant__ __align__(16) float c_w[H];
__constant__ float c_simb[1];

// ---------------- adapter: 1 warp = 2 rows; each weight LDG.64 feeds BOTH rows ----------------
template <int DIN, bool IS_TARGET>
__device__ __forceinline__ void adapter_row2(
    int row0, int tj,
    const float* __restrict__ X,
    const float* __restrict__ W1, const float* __restrict__ b1,
    const float* __restrict__ g,  const float* __restrict__ beta,
    const float* __restrict__ W2, const float* __restrict__ b2,
    const float* __restrict__ cWpart, const float* __restrict__ cb,
    float* sxA, float* sxB, float* srA, float* srB, float* saA, float* saB)
{
    const int j2 = 2 * tj;
    const int row1 = row0 + 1;

    // stage both x rows (warp-private smem)
    if (DIN == 128) {
        ((float4*)sxA)[tj] = ((const float4*)(X + (size_t)row0 * DIN))[tj];
        ((float4*)sxB)[tj] = ((const float4*)(X + (size_t)row1 * DIN))[tj];
    } else {
        ((float2*)sxA)[tj] = ((const float2*)(X + (size_t)row0 * DIN))[tj];
        ((float2*)sxB)[tj] = ((const float2*)(X + (size_t)row1 * DIN))[tj];
    }
    __syncwarp();

    // layer 1: weights shared across both rows (1 LDG.64 -> 2 fma2)
    ull hA0 = 0ull, hA1 = 0ull, hB0 = 0ull, hB1 = 0ull;
#pragma unroll
    for (int k = 0; k < DIN; k += 2) {
        ull w0 = *(const ull*)&W1[(size_t)(k)     * H + j2];
        ull w1 = *(const ull*)&W1[(size_t)(k + 1) * H + j2];
        hA0 = fma2(pack2(sxA[k],     sxA[k]),     w0, hA0);
        hB0 = fma2(pack2(sxB[k],     sxB[k]),     w0, hB0);
        hA1 = fma2(pack2(sxA[k + 1], sxA[k + 1]), w1, hA1);
        hB1 = fma2(pack2(sxB[k + 1], sxB[k + 1]), w1, hB1);
    }
    float2 hA = unpack2(add2(hA0, hA1));
    float2 hB = unpack2(add2(hB0, hB1));
    {
        float2 bv = *(const float2*)&b1[j2];
        hA.x += bv.x; hA.y += bv.y;
        hB.x += bv.x; hB.y += bv.y;
    }

    // LN stats for both rows (4 shuffle chains)
    float sA1 = hA.x + hA.y, sA2 = hA.x * hA.x + hA.y * hA.y;
    float sB1 = hB.x + hB.y, sB2 = hB.x * hB.x + hB.y * hB.y;
#pragma unroll
    for (int o = 16; o; o >>= 1) {
        sA1 += __shfl_xor_sync(~0u, sA1, o);
        sA2 += __shfl_xor_sync(~0u, sA2, o);
        sB1 += __shfl_xor_sync(~0u, sB1, o);
        sB2 += __shfl_xor_sync(~0u, sB2, o);
    }
    {
        const float mA   = sA1 * (1.f / H);
        const float invA = rsqrtf(sA2 * (1.f / H) - mA * mA + LN_EPS);
        const float mB   = sB1 * (1.f / H);
        const float invB = rsqrtf(sB2 * (1.f / H) - mB * mB + LN_EPS);
        float2 gv  = *(const float2*)&g[j2];
        float2 bev = *(const float2*)&beta[j2];
        *(float2*)&srA[j2] = make_float2(fmaxf((hA.x - mA) * invA * gv.x + bev.x, 0.f),
                                         fmaxf((hA.y - mA) * invA * gv.y + bev.y, 0.f));
        *(float2*)&srB[j2] = make_float2(fmaxf((hB.x - mB) * invB * gv.x + bev.x, 0.f),
                                         fmaxf((hB.y - mB) * invB * gv.y + bev.y, 0.f));
    }
    __syncwarp();

    // layer 2 (shared weights)
    ull aA0 = 0ull, aA1 = 0ull, aB0 = 0ull, aB1 = 0ull;
#pragma unroll
    for (int k = 0; k < H; k += 2) {
        ull w0 = *(const ull*)&W2[(size_t)(k)     * H + j2];
        ull w1 = *(const ull*)&W2[(size_t)(k + 1) * H + j2];
        aA0 = fma2(pack2(srA[k],     srA[k]),     w0, aA0);
        aB0 = fma2(pack2(srB[k],     srB[k]),     w0, aB0);
        aA1 = fma2(pack2(srA[k + 1], srA[k + 1]), w1, aA1);
        aB1 = fma2(pack2(srB[k + 1], srB[k + 1]), w1, aB1);
    }
    float2 adA = unpack2(add2(aA0, aA1));
    float2 adB = unpack2(add2(aB0, aB1));
    {
        float2 bv = *(const float2*)&b2[j2];
        adA.x += bv.x; adA.y += bv.y;
        adB.x += bv.x; adB.y += bv.y;
    }

    if (IS_TARGET) {
        *(float2*)&g_t_ad[(size_t)row0 * H + j2] = adA;
        *(float2*)&g_t_ad[(size_t)row1 * H + j2] = adB;
    } else {
        *(float2*)&g_s_ad[(size_t)row0 * H + j2] = adA;
        *(float2*)&g_s_ad[(size_t)row1 * H + j2] = adB;
    }
    *(float2*)&saA[j2] = adA;
    *(float2*)&saB[j2] = adB;

    if (IS_TARGET) {
        float sA = adA.x + adA.y, sB = adB.x + adB.y;
#pragma unroll
        for (int o = 16; o; o >>= 1) {
            sA += __shfl_xor_sync(~0u, sA, o);
            sB += __shfl_xor_sync(~0u, sB, o);
        }
        if (tj == 0) {
            g_gate[row0] = 1.f / (1.f + __expf(-sA * (1.f / H)));
            g_gate[row1] = 1.f / (1.f + __expf(-sB * (1.f / H)));
        }
    }
    __syncwarp();

    // projection (shared weights)
    ull pA0, pA1 = 0ull, pB0, pB1 = 0ull;
    if (IS_TARGET) {
        float2 cbv = *(const float2*)&cb[j2];
        pA0 = pack2(cbv.x, cbv.y);
        pB0 = pA0;
    } else { pA0 = 0ull; pB0 = 0ull; }
#pragma unroll
    for (int k = 0; k < H; k += 2) {
        ull w0 = *(const ull*)&cWpart[(size_t)(k)     * H + j2];
        ull w1 = *(const ull*)&cWpart[(size_t)(k + 1) * H + j2];
        pA0 = fma2(pack2(saA[k],     saA[k]),     w0, pA0);
        pB0 = fma2(pack2(saB[k],     saB[k]),     w0, pB0);
        pA1 = fma2(pack2(saA[k + 1], saA[k + 1]), w1, pA1);
        pB1 = fma2(pack2(saB[k + 1], saB[k + 1]), w1, pB1);
    }
    float2 pA = unpack2(add2(pA0, pA1));
    float2 pB = unpack2(add2(pB0, pB1));

    if (IS_TARGET) {
        *(float2*)&g_a[(size_t)row0 * H + j2] = pA;
        *(float2*)&g_a[(size_t)row1 * H + j2] = pB;
    } else {
        *(float2*)&g_u[(size_t)row0 * H + j2] = pA;
        *(float2*)&g_u[(size_t)row1 * H + j2] = pB;
    }

    float qA1 = pA.x + pA.y, qA2 = pA.x * pA.x + pA.y * pA.y;
    float qB1 = pB.x + pB.y, qB2 = pB.x * pB.x + pB.y * pB.y;
#pragma unroll
    for (int o = 16; o; o >>= 1) {
        qA1 += __shfl_xor_sync(~0u, qA1, o);
        qA2 += __shfl_xor_sync(~0u, qA2, o);
        qB1 += __shfl_xor_sync(~0u, qB1, o);
        qB2 += __shfl_xor_sync(~0u, qB2, o);
    }
    if (tj == 0) {
        if (IS_TARGET) {
            g_sum_a[row0] = qA1; g_sa2[row0] = qA2;
            g_sum_a[row1] = qB1; g_sa2[row1] = qB2;
        } else {
            g_sum_u[row0] = qA1; g_su2[row0] = qA2;
            g_sum_u[row1] = qB1; g_su2[row1] = qB2;
        }
    }
}

// ---------------- fused adapters: 8 warps x 2 rows = 16 rows per 256-thread block ----------
__global__ __launch_bounds__(256)
void adapters_fused(const float* __restrict__ src, const float* __restrict__ tgt,
                    const float* __restrict__ sW1, const float* __restrict__ sb1,
                    const float* __restrict__ sg,  const float* __restrict__ sbeta,
                    const float* __restrict__ sW2, const float* __restrict__ sb2,
                    const float* __restrict__ tW1, const float* __restrict__ tb1,
                    const float* __restrict__ tgam, const float* __restrict__ tbeta,
                    const float* __restrict__ tW2, const float* __restrict__ tb2,
                    const float* __restrict__ cW,  const float* __restrict__ cb)
{
    __shared__ __align__(16) float sh_x[16][DS];
    __shared__ __align__(16) float sh_r[16][H];
    __shared__ __align__(16) float sh_ad[16][H];

    const int wid = threadIdx.x >> 5;   // warp -> row pair
    const int tj  = threadIdx.x & 31;
    const int SRC_BLOCKS = BB * SS / 16;

    if (blockIdx.x < SRC_BLOCKS) {
        int row0 = (blockIdx.x * 8 + wid) * 2;
        adapter_row2<DS, false>(row0, tj, src, sW1, sb1, sg, sbeta, sW2, sb2,
                                cW + H * H, nullptr,
                                sh_x[2 * wid], sh_x[2 * wid + 1],
                                sh_r[2 * wid], sh_r[2 * wid + 1],
                                sh_ad[2 * wid], sh_ad[2 * wid + 1]);
    } else {
        int row0 = ((blockIdx.x - SRC_BLOCKS) * 8 + wid) * 2;
        adapter_row2<DT, true>(row0, tj, tgt, tW1, tb1, tgam, tbeta, tW2, tb2,
                               cW, cb,
                               sh_x[2 * wid], sh_x[2 * wid + 1],
                               sh_r[2 * wid], sh_r[2 * wid + 1],
                               sh_ad[2 * wid], sh_ad[2 * wid + 1]);
    }
}

// ---------------- score kernel: CH=32, 3-buffer ring (proven) ----------------
__global__ __launch_bounds__(256, 2)
void score_kernel(float* __restrict__ out_scores)
{
    __shared__ __align__(16) float u_sh[3][CH * USTRIDE];
    __shared__ __align__(16) float a_sh[TILE_T][H];

    const int tid = threadIdx.x;
    const int lane = tid & 31;
    const int w = tid >> 5;
    const int tglob = blockIdx.x * TILE_T + w;
    const int b = tglob >> 10;
    const int srow0 = b << 10;

    ((float2*)a_sh[w])[lane] = ((const float2*)(g_a + (size_t)tglob * H))[lane];

    const float suma = g_sum_a[tglob];
    const float sqa  = g_sa2[tglob];
    const float simb0 = c_simb[0];

    {
        const float4* src = (const float4*)(g_u + (size_t)srow0 * H);
#pragma unroll
        for (int rep = 0; rep < 2; rep++) {
            int f = tid + rep * 256;
            int r = f >> 4, q = f & 15;
            cp16(&u_sh[0][r * USTRIDE + q * 4], src + f);
        }
        asm volatile("cp.async.commit_group;");
    }

    float* srow_out = out_scores + (size_t)tglob * SS;

    int buf = 0;
    for (int c = 0; c < SS / CH; c++) {
        if (c < SS / CH - 1) {
            const float4* src = (const float4*)(g_u + (size_t)(srow0 + (c + 1) * CH) * H);
            float* dst = u_sh[(buf + 1) % 3];
#pragma unroll
            for (int rep = 0; rep < 2; rep++) {
                int f = tid + rep * 256;
                int r = f >> 4, q = f & 15;
                cp16(&dst[r * USTRIDE + q * 4], src + f);
            }
            asm volatile("cp.async.commit_group;");
            asm volatile("cp.async.wait_group 1;");
        } else {
            asm volatile("cp.async.wait_group 0;");
        }
        __syncthreads();

        const ulonglong2* up2 = (const ulonglong2*)&u_sh[buf][lane * USTRIDE];
        ull u2[H / 2];
#pragma unroll
        for (int i = 0; i < H / 4; i++) {
            ulonglong2 v = up2[i];
            u2[2 * i] = v.x; u2[2 * i + 1] = v.y;
        }

        const int sidx = srow0 + c * CH + lane;
        const float su  = g_sum_u[sidx];
        const float squ = g_su2[sidx];

        const ulonglong2* ap2 = (const ulonglong2*)a_sh[w];

        ull d0 = 0ull, d1 = 0ull, d2 = 0ull, d3 = 0ull;
#pragma unroll
        for (int i = 0; i < H / 4; i += 2) {
            ulonglong2 aa = ap2[i];
            ulonglong2 ab = ap2[i + 1];
            d0 = fma2(aa.x, u2[2 * i],     d0);
            d1 = fma2(aa.y, u2[2 * i + 1], d1);
            d2 = fma2(ab.x, u2[2 * i + 2], d2);
            d3 = fma2(ab.y, u2[2 * i + 3], d3);
        }
        float2 f0 = unpack2(d0), f1 = unpack2(d1), f2 = unpack2(d2), f3 = unpack2(d3);
        const float dot = ((f0.x + f0.y) + (f1.x + f1.y)) + ((f2.x + f2.y) + (f3.x + f3.y));

        const float m   = (suma + su) * (1.f / H);
        const float e2  = (sqa + 2.f * dot + squ) * (1.f / H);
        const float inv = rsqrtf(e2 - m * m + LN_EPS);
        const float nm  = -m * inv;
        const ull inv2 = pack2(inv, inv);
        const ull nm2  = pack2(nm, nm);

        ull acca = 0ull, accb = 0ull;
#pragma unroll
        for (int i = 0; i < H / 4; i++) {
            ulonglong2 aa  = ap2[i];
            ulonglong2 kcg = *(const ulonglong2*)&c_cg[4 * i];
            ulonglong2 kcb = *(const ulonglong2*)&c_cb[4 * i];
            ulonglong2 kw  = *(const ulonglong2*)&c_w[4 * i];
            ull p0 = add2(aa.x, u2[2 * i]);
            ull p1 = add2(aa.y, u2[2 * i + 1]);
            ull z0 = fma2(p0, inv2, nm2);
            ull z1 = fma2(p1, inv2, nm2);
            ull y0 = fma2(z0, kcg.x, kcb.x);
            ull y1 = fma2(z1, kcg.y, kcb.y);
            float2 ya = unpack2(y0), yb = unpack2(y1);
            ya.x = fmaxf(ya.x, 0.f); ya.y = fmaxf(ya.y, 0.f);
            yb.x = fmaxf(yb.x, 0.f); yb.y = fmaxf(yb.y, 0.f);
            acca = fma2(pack2(ya.x, ya.y), kw.x, acca);
            accb = fma2(pack2(yb.x, yb.y), kw.y, accb);
        }
        float2 sa2 = unpack2(acca), sb2 = unpack2(accb);
        const float acc = (sa2.x + sa2.y) + (sb2.x + sb2.y);
        const float score = 1.f / (1.f + __expf(-(acc + simb0)));
        srow_out[c * CH + lane] = score;

        buf = (buf + 1) % 3;
    }
}

// ---------------- transfer: 256 thr / 8 warps, TTG=8; e2/red smem UNION (16KB) ----------
__global__ __launch_bounds__(256)
void transfer_kernel(const float* __restrict__ scores, float* __restrict__ out_adapted)
{
    __shared__ __align__(16) ull sh[8][32 * TTG];   // 16KB; e2 view phase1, red view phase2
    __shared__ float sums_sh[8][TTG];

    const int tid = threadIdx.x;
    const int w = tid >> 5, lane = tid & 31;
    const int tbase = blockIdx.x * TTG;
    const int b = tbase >> 10;
    const int srow0 = b << 10;

    ull acc2[TTG];
    float se[TTG];
#pragma unroll
    for (int t = 0; t < TTG; t++) { acc2[t] = 0ull; se[t] = 0.f; }

    for (int c = 0; c < 4; c++) {
        const int sloc0 = w * 128 + c * 32;

#pragma unroll
        for (int t = 0; t < TTG; t++) {
            float e = __expf(scores[(size_t)(tbase + t) * SS + sloc0 + lane]);
            se[t] += e;
            sh[w][lane * TTG + t] = pack2(e, e);
        }
        __syncwarp();

#pragma unroll 4
        for (int j = 0; j < 32; j += 8) {
            ull v[8];
#pragma unroll
            for (int k = 0; k < 8; k++)
                v[k] = *(const ull*)(g_s_ad + (size_t)(srow0 + sloc0 + j + k) * H + 2 * lane);
#pragma unroll
            for (int k = 0; k < 8; k++) {
                const ulonglong2* ep = (const ulonglong2*)&sh[w][(j + k) * TTG];
                ulonglong2 e01 = ep[0], e23 = ep[1], e45 = ep[2], e67 = ep[3];
                acc2[0] = fma2(v[k], e01.x, acc2[0]);
                acc2[1] = fma2(v[k], e01.y, acc2[1]);
                acc2[2] = fma2(v[k], e23.x, acc2[2]);
                acc2[3] = fma2(v[k], e23.y, acc2[3]);
                acc2[4] = fma2(v[k], e45.x, acc2[4]);
                acc2[5] = fma2(v[k], e45.y, acc2[5]);
                acc2[6] = fma2(v[k], e67.x, acc2[6]);
                acc2[7] = fma2(v[k], e67.y, acc2[7]);
            }
        }
        __syncwarp();
    }

#pragma unroll
    for (int t = 0; t < TTG; t++) {
        float s = se[t];
#pragma unroll
        for (int o = 16; o; o >>= 1) s += __shfl_xor_sync(~0u, s, o);
        if (lane == 0) sums_sh[w][t] = s;
    }

    float* red = (float*)sh;
#pragma unroll
    for (int t = 0; t < TTG; t++)
        *(ull*)&red[(w * TTG + t) * H + 2 * lane] = acc2[t];
    __syncthreads();

    const int t = tid >> 5;
    const int hp = (tid & 31) * 2;
    float sx = 0.f, sy = 0.f;
#pragma unroll
    for (int ww = 0; ww < 8; ww++) {
        float2 p = unpack2(*(const ull*)&red[(ww * TTG + t) * H + hp]);
        sx += p.x; sy += p.y;
    }
    float sumexp = 0.f;
#pragma unroll
    for (int ww = 0; ww < 8; ww++) sumexp += sums_sh[ww][t];

    const int tg = tbase + t;
    const float rs = 1.f / sumexp;
    const float gt = g_gate[tg];
    const float2 ta = *(const float2*)&g_t_ad[(size_t)tg * H + hp];
    float2 o;
    o.x = ta.x * (1.f - gt) + sx * rs * gt;
    o.y = ta.y * (1.f - gt) + sy * rs * gt;
    *(float2*)&out_adapted[(size_t)tg * H + hp] = o;
}

// ---------------- launch ----------------
extern "C" void kernel_launch(void* const* d_in, const int* in_sizes, int n_in,
                              void* d_out, int out_size)
{
    (void)in_sizes; (void)n_in; (void)out_size;
    const float* src   = (const float*)d_in[0];
    const float* tgt   = (const float*)d_in[1];
    const float* sW1   = (const float*)d_in[2];
    const float* sb1   = (const float*)d_in[3];
    const float* sg    = (const float*)d_in[4];
    const float* sbeta = (const float*)d_in[5];
    const float* sW2   = (const float*)d_in[6];
    const float* sb2   = (const float*)d_in[7];
    const float* tW1   = (const float*)d_in[8];
    const float* tb1   = (const float*)d_in[9];
    const float* tg    = (const float*)d_in[10];
    const float* tbeta = (const float*)d_in[11];
    const float* tW2   = (const float*)d_in[12];
    const float* tb2   = (const float*)d_in[13];
    const float* cW    = (const float*)d_in[14];
    const float* cb    = (const float*)d_in[15];
    const float* cg    = (const float*)d_in[16];
    const float* cbeta = (const float*)d_in[17];
    const float* simW  = (const float*)d_in[18];
    const float* simb  = (const float*)d_in[19];

    float* out_adapted = (float*)d_out;                      // (B,T,H)
    float* out_scores  = out_adapted + (size_t)BB * TT * H;  // (B,T,S)

    cudaMemcpyToSymbolAsync(c_cg,   cg,    H * sizeof(float), 0, cudaMemcpyDeviceToDevice, 0);
    cudaMemcpyToSymbolAsync(c_cb,   cbeta, H * sizeof(float), 0, cudaMemcpyDeviceToDevice, 0);
    cudaMemcpyToSymbolAsync(c_w,    simW,  H * sizeof(float), 0, cudaMemcpyDeviceToDevice, 0);
    cudaMemcpyToSymbolAsync(c_simb, simb,  sizeof(float),     0, cudaMemcpyDeviceToDevice, 0);

    adapters_fused<<<BB * SS / 16 + BB * TT / 16, 256>>>(src, tgt,
                                                         sW1, sb1, sg, sbeta, sW2, sb2,
                                                         tW1, tb1, tg, tbeta, tW2, tb2,
                                                         cW, cb);
    score_kernel<<<(BB * TT) / TILE_T, 256>>>(out_scores);
    transfer_kernel<<<(BB * TT) / TTG, 256>>>(out_scores, out_adapted);
}